// round 4
// baseline (speedup 1.0000x reference)
// QLSTM: quantum-gate LSTM, T=2048, B=256, D=128, H=NQ=4.
//
// Decomposition:
//   Kernel 1 (qlstm_gemm): pre[t,b,16] = x[t,b,:]@W_g[:128,:] + b_g + theta_g
//       (input-dependent part of all 4 gates; parallel over all T*B rows)
//   Kernel 2 (qlstm_scan): serial LSTM recurrence. 4 threads per batch element
//       (one per gate); quad exchanges activations via warp shuffles.
//
// qlayer(x, theta) = cumprod(cos(x + theta)); theta/bias folded into pre.
// sigmoid(p) = 0.5 + 0.5*tanh(0.5 p); tanh via Eigen/XLA rational (valid |x|<7.9;
// our args are bounded: cumprod in [-1,1], c in [-2.1,2.1]).

#include <cuda_runtime.h>
#include <cstdint>

#define TT 2048
#define BB 256
#define DD 128
#define ROWS (TT * BB)   // 524288

// scratch: pre-activations for all gates, [T][B][16], 33.5 MB (fits in L2)
__device__ __align__(128) float g_pre[ROWS * 16];

// ---------------------------------------------------------------------------
// fast tanh: Eigen/XLA rational approximation, |x| <= ~7.9, rel err < 1e-6
// ---------------------------------------------------------------------------
__device__ __forceinline__ float tanh_fast(float x) {
    float y = x * x;
    float p = fmaf(y, -2.76076847742355e-16f, 2.00018790482477e-13f);
    p = fmaf(y, p, -8.60467152213735e-11f);
    p = fmaf(y, p, 5.12229709037114e-08f);
    p = fmaf(y, p, 1.48572235717979e-05f);
    p = fmaf(y, p, 6.37261928875436e-04f);
    p = fmaf(y, p, 4.89352455891786e-03f);
    p = p * x;
    float q = fmaf(y, 1.19825839466702e-06f, 1.18534705686654e-04f);
    q = fmaf(y, q, 2.26843463243900e-03f);
    q = fmaf(y, q, 4.89352518554385e-03f);
    return __fdividef(p, q);
}

// ---------------------------------------------------------------------------
// f32x2 packed helpers (Blackwell)
// ---------------------------------------------------------------------------
__device__ __forceinline__ unsigned long long pk2(float lo, float hi) {
    unsigned long long r;
    asm("mov.b64 %0, {%1, %2};" : "=l"(r) : "f"(lo), "f"(hi));
    return r;
}
__device__ __forceinline__ void upk2(unsigned long long v, float& lo, float& hi) {
    asm("mov.b64 {%0, %1}, %2;" : "=f"(lo), "=f"(hi) : "l"(v));
}
__device__ __forceinline__ unsigned long long fma2(unsigned long long a,
                                                   unsigned long long b,
                                                   unsigned long long c) {
    unsigned long long d;
    asm("fma.rn.f32x2 %0, %1, %2, %3;" : "=l"(d) : "l"(a), "l"(b), "l"(c));
    return d;
}

// ---------------------------------------------------------------------------
// Kernel 1: pre[row][g*4+k] = sum_j x[row][j]*W_g[j][k] + b_g[k] + theta_g[k]
// Block: 128 threads, tile = 64 rows x 128 cols in smem.
// Thread = (row = tid>>1, k-half = (tid&1)*8), f32x2 accumulators.
// ---------------------------------------------------------------------------
__global__ __launch_bounds__(128) void qlstm_gemm(
    const float* __restrict__ x,
    const float* __restrict__ W0, const float* __restrict__ b0, const float* __restrict__ q0,
    const float* __restrict__ W1, const float* __restrict__ b1, const float* __restrict__ q1,
    const float* __restrict__ W2, const float* __restrict__ b2, const float* __restrict__ q2,
    const float* __restrict__ W3, const float* __restrict__ b3, const float* __restrict__ q3)
{
    __shared__ __align__(16) float xs[64 * 132];   // row stride 132 -> conflict-free
    __shared__ __align__(16) float ws[128 * 16];   // combined weights [j][g*4+k]
    __shared__ float bt[16];                       // bias + theta folded

    int tid = threadIdx.x;

    // stage combined W into smem
    for (int idx = tid; idx < 2048; idx += 128) {
        int j = idx >> 4, c = idx & 15, gg = c >> 2, k = c & 3;
        const float* W = (gg == 0) ? W0 : (gg == 1) ? W1 : (gg == 2) ? W2 : W3;
        ws[j * 16 + c] = W[j * 4 + k];
    }
    if (tid < 16) {
        int gg = tid >> 2, k = tid & 3;
        const float* bb = (gg == 0) ? b0 : (gg == 1) ? b1 : (gg == 2) ? b2 : b3;
        const float* qq = (gg == 0) ? q0 : (gg == 1) ? q1 : (gg == 2) ? q2 : q3;
        bt[tid] = bb[k] + qq[k];
    }

    // stage 64 rows of x, fully coalesced float4 loads
    size_t row0 = (size_t)blockIdx.x * 64;
    const float4* xin = (const float4*)x + row0 * 32;
    #pragma unroll
    for (int i = 0; i < 16; i++) {
        int idx = tid + i * 128;
        int fr = idx >> 5, c4 = idx & 31;
        float4 v = xin[idx];
        *(float4*)&xs[fr * 132 + c4 * 4] = v;
    }
    __syncthreads();

    int row = tid >> 1;
    int kb = (tid & 1) * 8;

    unsigned long long acc[4];
    #pragma unroll
    for (int p = 0; p < 4; p++)
        acc[p] = pk2(bt[kb + 2 * p], bt[kb + 2 * p + 1]);

    #pragma unroll 4
    for (int j = 0; j < 128; j += 4) {
        float4 xv = *(const float4*)&xs[row * 132 + j];
        float xr[4] = {xv.x, xv.y, xv.z, xv.w};
        #pragma unroll
        for (int jj = 0; jj < 4; jj++) {
            unsigned long long xp = pk2(xr[jj], xr[jj]);
            const ulonglong2* wp = (const ulonglong2*)&ws[(j + jj) * 16 + kb];
            ulonglong2 wa = wp[0];
            ulonglong2 wb = wp[1];
            acc[0] = fma2(xp, wa.x, acc[0]);
            acc[1] = fma2(xp, wa.y, acc[1]);
            acc[2] = fma2(xp, wb.x, acc[2]);
            acc[3] = fma2(xp, wb.y, acc[3]);
        }
    }

    float4 r0, r1;
    upk2(acc[0], r0.x, r0.y);
    upk2(acc[1], r0.z, r0.w);
    upk2(acc[2], r1.x, r1.y);
    upk2(acc[3], r1.z, r1.w);
    float4* dst = (float4*)&g_pre[(row0 + row) * 16 + kb];
    dst[0] = r0;
    dst[1] = r1;
}

// ---------------------------------------------------------------------------
// Kernel 2: serial scan. 32 blocks x 32 threads; lane = (local_batch<<2)|gate.
// Each thread owns one gate of one batch element; quad exchanges via shfl.
// ---------------------------------------------------------------------------
__global__ __launch_bounds__(32) void qlstm_scan(
    const float* __restrict__ W0, const float* __restrict__ W1,
    const float* __restrict__ W2, const float* __restrict__ W3,
    float* __restrict__ out)
{
    const unsigned FULL = 0xffffffffu;
    int lane = threadIdx.x;
    int g    = lane & 3;
    int b    = (int)blockIdx.x * 8 + (lane >> 2);
    int base = lane & ~3;

    // recurrent weights W[128+j][k] for this gate
    const float* W = (g == 0) ? W0 : (g == 1) ? W1 : (g == 2) ? W2 : W3;
    float wh[4][4];
    #pragma unroll
    for (int j = 0; j < 4; j++)
        #pragma unroll
        for (int k = 0; k < 4; k++)
            wh[j][k] = W[(DD + j) * 4 + k];

    // activation: gate 2 (update) -> tanh(p); others -> sigmoid(p)=0.5+0.5*tanh(0.5p)
    float pm  = (g == 2) ? 1.0f : 0.5f;
    float ab  = (g == 2) ? 0.0f : 0.5f;
    float asc = (g == 2) ? 1.0f : 0.5f;

    float h0 = 0.f, h1 = 0.f, h2 = 0.f, h3 = 0.f;
    float c0 = 0.f, c1 = 0.f, c2 = 0.f, c3 = 0.f;

    // pre[t][b][g*4 .. g*4+3] as float4; per-t stride = 1024 float4s
    const float4* pre4 = (const float4*)g_pre + (size_t)b * 4 + g;
    float4 cur = pre4[0];
    float4 nxt = pre4[1024];
    float* outp = out + (size_t)b * 4;

    for (int t = 0; t < TT; t++) {
        float4 zz = cur;
        cur = nxt;
        int tn = t + 2;
        if (tn >= TT) tn = TT - 1;
        nxt = pre4[(size_t)tn * 1024];          // prefetch 2 steps ahead (L2)

        // z = pre + h @ Wh  (16 FMA)
        float z0 = zz.x, z1 = zz.y, z2 = zz.z, z3 = zz.w;
        z0 = fmaf(h0, wh[0][0], z0); z1 = fmaf(h0, wh[0][1], z1);
        z2 = fmaf(h0, wh[0][2], z2); z3 = fmaf(h0, wh[0][3], z3);
        z0 = fmaf(h1, wh[1][0], z0); z1 = fmaf(h1, wh[1][1], z1);
        z2 = fmaf(h1, wh[1][2], z2); z3 = fmaf(h1, wh[1][3], z3);
        z0 = fmaf(h2, wh[2][0], z0); z1 = fmaf(h2, wh[2][1], z1);
        z2 = fmaf(h2, wh[2][2], z2); z3 = fmaf(h2, wh[2][3], z3);
        z0 = fmaf(h3, wh[3][0], z0); z1 = fmaf(h3, wh[3][1], z1);
        z2 = fmaf(h3, wh[3][2], z2); z3 = fmaf(h3, wh[3][3], z3);

        // qlayer: cumulative product of cosines
        float p0 = __cosf(z0);
        float p1 = p0 * __cosf(z1);
        float p2 = p1 * __cosf(z2);
        float p3 = p2 * __cosf(z3);

        // gate activation
        float a0 = fmaf(asc, tanh_fast(pm * p0), ab);
        float a1 = fmaf(asc, tanh_fast(pm * p1), ab);
        float a2 = fmaf(asc, tanh_fast(pm * p2), ab);
        float a3 = fmaf(asc, tanh_fast(pm * p3), ab);

        // quad exchange: grab all 4 gates' activation vectors (static reg slots)
        float f0v = __shfl_sync(FULL, a0, base);
        float f1v = __shfl_sync(FULL, a1, base);
        float f2v = __shfl_sync(FULL, a2, base);
        float f3v = __shfl_sync(FULL, a3, base);
        float i0v = __shfl_sync(FULL, a0, base + 1);
        float i1v = __shfl_sync(FULL, a1, base + 1);
        float i2v = __shfl_sync(FULL, a2, base + 1);
        float i3v = __shfl_sync(FULL, a3, base + 1);
        float u0v = __shfl_sync(FULL, a0, base + 2);
        float u1v = __shfl_sync(FULL, a1, base + 2);
        float u2v = __shfl_sync(FULL, a2, base + 2);
        float u3v = __shfl_sync(FULL, a3, base + 2);
        float o0v = __shfl_sync(FULL, a0, base + 3);
        float o1v = __shfl_sync(FULL, a1, base + 3);
        float o2v = __shfl_sync(FULL, a2, base + 3);
        float o3v = __shfl_sync(FULL, a3, base + 3);

        // c = f*c + i*g   (identical across the quad -> consistent)
        c0 = fmaf(f0v, c0, i0v * u0v);
        c1 = fmaf(f1v, c1, i1v * u1v);
        c2 = fmaf(f2v, c2, i2v * u2v);
        c3 = fmaf(f3v, c3, i3v * u3v);

        // each lane computes only its own h component, then broadcast
        float cg = (g & 2) ? ((g & 1) ? c3 : c2) : ((g & 1) ? c1 : c0);
        float og = (g & 2) ? ((g & 1) ? o3v : o2v) : ((g & 1) ? o1v : o0v);
        float hm = og * tanh_fast(cg);
        h0 = __shfl_sync(FULL, hm, base);
        h1 = __shfl_sync(FULL, hm, base + 1);
        h2 = __shfl_sync(FULL, hm, base + 2);
        h3 = __shfl_sync(FULL, hm, base + 3);

        if (g == 0)
            *(float4*)(outp + (size_t)t * (BB * 4)) = make_float4(h0, h1, h2, h3);
    }

    // trailing hx / cx blocks of the tuple output
    if (g == 0) {
        float* hxp = out + (size_t)TT * BB * 4 + (size_t)b * 4;
        *(float4*)hxp = make_float4(h0, h1, h2, h3);
        float* cxp = out + (size_t)TT * BB * 4 + (size_t)BB * 4 + (size_t)b * 4;
        *(float4*)cxp = make_float4(c0, c1, c2, c3);
    }
}

// ---------------------------------------------------------------------------
extern "C" void kernel_launch(void* const* d_in, const int* in_sizes, int n_in,
                              void* d_out, int out_size) {
    const float* x  = (const float*)d_in[0];
    const float* Wf = (const float*)d_in[1];
    const float* bf = (const float*)d_in[2];
    const float* qf = (const float*)d_in[3];
    const float* Wi = (const float*)d_in[4];
    const float* bi = (const float*)d_in[5];
    const float* qi = (const float*)d_in[6];
    const float* Wu = (const float*)d_in[7];
    const float* bu = (const float*)d_in[8];
    const float* qu = (const float*)d_in[9];
    const float* Wo = (const float*)d_in[10];
    const float* bo = (const float*)d_in[11];
    const float* qo = (const float*)d_in[12];

    qlstm_gemm<<<ROWS / 64, 128>>>(x, Wf, bf, qf, Wi, bi, qi, Wu, bu, qu, Wo, bo, qo);
    qlstm_scan<<<BB / 8, 32>>>(Wf, Wi, Wu, Wo, (float*)d_out);
}

// round 7
// speedup vs baseline: 1.2356x; 1.2356x over previous
// QLSTM: quantum-gate LSTM, T=2048, B=256, D=128, H=NQ=4.
//
// Kernel 1 (qlstm_gemm): pre[t,b,16] = x[t,b,:]@W_g[:128,:] + b_g + theta_g
// Kernel 2 (qlstm_scan): serial recurrence; 4 lanes per batch element (one per
//   gate). ONE shuffle round per step (activation exchange); every lane then
//   redundantly computes the full c/h update so no h-broadcast round is needed.
//
// qlayer(x, theta) = cumprod(cos(x + theta)); theta/bias folded into pre.
// Gate activations via MUFU.TANH (tanh.approx.f32); tanh(c) via ex2+rcp
// (precise) since its error integrates through the recurrence.

#include <cuda_runtime.h>
#include <cstdint>

#define TT 2048
#define BB 256
#define DD 128
#define ROWS (TT * BB)   // 524288

// scratch: pre-activations [T][B][16] + 2 timesteps of padding so the scan's
// prefetch (t+2) never needs a clamp.
__device__ __align__(128) float g_pre[(TT + 2) * BB * 16];

// ---------------------------------------------------------------------------
// math helpers
// ---------------------------------------------------------------------------
__device__ __forceinline__ float tanh_hw(float x) {          // MUFU.TANH
    float r;
    asm("tanh.approx.f32 %0, %1;" : "=f"(r) : "f"(x));
    return r;
}
__device__ __forceinline__ float rcp_fast(float x) {         // MUFU.RCP
    float r;
    asm("rcp.approx.f32 %0, %1;" : "=f"(r) : "f"(x));
    return r;
}
__device__ __forceinline__ float ex2_fast(float x) {         // MUFU.EX2
    float r;
    asm("ex2.approx.f32 %0, %1;" : "=f"(r) : "f"(x));
    return r;
}
// precise-ish tanh via exp2: tanh(x) = 1 - 2/(1 + e^{2x}); |x| <= ~2.2 here.
__device__ __forceinline__ float tanh_exp(float x) {
    float e = ex2_fast(x * 2.8853900817779268f);  // 2*log2(e)
    float r = rcp_fast(e + 1.0f);
    return fmaf(-2.0f, r, 1.0f);
}

// f32x2 packed helpers (Blackwell)
__device__ __forceinline__ unsigned long long pk2(float lo, float hi) {
    unsigned long long r;
    asm("mov.b64 %0, {%1, %2};" : "=l"(r) : "f"(lo), "f"(hi));
    return r;
}
__device__ __forceinline__ void upk2(unsigned long long v, float& lo, float& hi) {
    asm("mov.b64 {%0, %1}, %2;" : "=f"(lo), "=f"(hi) : "l"(v));
}
__device__ __forceinline__ unsigned long long fma2(unsigned long long a,
                                                   unsigned long long b,
                                                   unsigned long long c) {
    unsigned long long d;
    asm("fma.rn.f32x2 %0, %1, %2, %3;" : "=l"(d) : "l"(a), "l"(b), "l"(c));
    return d;
}

// ---------------------------------------------------------------------------
// Kernel 1: pre[row][g*4+k] = sum_j x[row][j]*W_g[j][k] + b_g[k] + theta_g[k]
// Block: 128 threads, tile = 64 rows x 128 cols in smem, f32x2 accumulators.
// ---------------------------------------------------------------------------
__global__ __launch_bounds__(128) void qlstm_gemm(
    const float* __restrict__ x,
    const float* __restrict__ W0, const float* __restrict__ b0, const float* __restrict__ q0,
    const float* __restrict__ W1, const float* __restrict__ b1, const float* __restrict__ q1,
    const float* __restrict__ W2, const float* __restrict__ b2, const float* __restrict__ q2,
    const float* __restrict__ W3, const float* __restrict__ b3, const float* __restrict__ q3)
{
    __shared__ __align__(16) float xs[64 * 132];
    __shared__ __align__(16) float ws[128 * 16];
    __shared__ float bt[16];

    int tid = threadIdx.x;

    for (int idx = tid; idx < 2048; idx += 128) {
        int j = idx >> 4, c = idx & 15, gg = c >> 2, k = c & 3;
        const float* W = (gg == 0) ? W0 : (gg == 1) ? W1 : (gg == 2) ? W2 : W3;
        ws[j * 16 + c] = W[j * 4 + k];
    }
    if (tid < 16) {
        int gg = tid >> 2, k = tid & 3;
        const float* bb = (gg == 0) ? b0 : (gg == 1) ? b1 : (gg == 2) ? b2 : b3;
        const float* qq = (gg == 0) ? q0 : (gg == 1) ? q1 : (gg == 2) ? q2 : q3;
        bt[tid] = bb[k] + qq[k];
    }

    size_t row0 = (size_t)blockIdx.x * 64;
    const float4* xin = (const float4*)x + row0 * 32;
    #pragma unroll
    for (int i = 0; i < 16; i++) {
        int idx = tid + i * 128;
        int fr = idx >> 5, c4 = idx & 31;
        float4 v = xin[idx];
        *(float4*)&xs[fr * 132 + c4 * 4] = v;
    }
    __syncthreads();

    int row = tid >> 1;
    int kb = (tid & 1) * 8;

    unsigned long long acc[4];
    #pragma unroll
    for (int p = 0; p < 4; p++)
        acc[p] = pk2(bt[kb + 2 * p], bt[kb + 2 * p + 1]);

    #pragma unroll 4
    for (int j = 0; j < 128; j += 4) {
        float4 xv = *(const float4*)&xs[row * 132 + j];
        float xr[4] = {xv.x, xv.y, xv.z, xv.w};
        #pragma unroll
        for (int jj = 0; jj < 4; jj++) {
            unsigned long long xp = pk2(xr[jj], xr[jj]);
            const ulonglong2* wp = (const ulonglong2*)&ws[(j + jj) * 16 + kb];
            ulonglong2 wa = wp[0];
            ulonglong2 wb = wp[1];
            acc[0] = fma2(xp, wa.x, acc[0]);
            acc[1] = fma2(xp, wa.y, acc[1]);
            acc[2] = fma2(xp, wb.x, acc[2]);
            acc[3] = fma2(xp, wb.y, acc[3]);
        }
    }

    float4 r0, r1;
    upk2(acc[0], r0.x, r0.y);
    upk2(acc[1], r0.z, r0.w);
    upk2(acc[2], r1.x, r1.y);
    upk2(acc[3], r1.z, r1.w);
    float4* dst = (float4*)&g_pre[(row0 + row) * 16 + kb];
    dst[0] = r0;
    dst[1] = r1;
}

// ---------------------------------------------------------------------------
// Kernel 2: serial scan. 32 blocks x 32 threads; lane = (local_batch<<2)|gate.
// One shuffle round per step; every lane redundantly computes c/h for all 4
// qubits, so no second broadcast round and no divergent branch.
// ---------------------------------------------------------------------------
__global__ __launch_bounds__(32) void qlstm_scan(
    const float* __restrict__ W0, const float* __restrict__ W1,
    const float* __restrict__ W2, const float* __restrict__ W3,
    float* __restrict__ out)
{
    const unsigned FULL = 0xffffffffu;
    int lane = threadIdx.x;
    int g    = lane & 3;
    int b    = (int)blockIdx.x * 8 + (lane >> 2);
    int base = lane & ~3;

    // recurrent weights for this gate, packed f32x2: wh2[j][half]
    const float* W = (g == 0) ? W0 : (g == 1) ? W1 : (g == 2) ? W2 : W3;
    unsigned long long wh2[4][2];
    #pragma unroll
    for (int j = 0; j < 4; j++) {
        wh2[j][0] = pk2(W[(DD + j) * 4 + 0], W[(DD + j) * 4 + 1]);
        wh2[j][1] = pk2(W[(DD + j) * 4 + 2], W[(DD + j) * 4 + 3]);
    }

    // activation params: gate 2 (update) -> tanh(p); others -> 0.5+0.5*tanh(0.5p)
    float pm  = (g == 2) ? 1.0f : 0.5f;
    float ab  = (g == 2) ? 0.0f : 0.5f;
    float asc = (g == 2) ? 1.0f : 0.5f;

    float h0 = 0.f, h1 = 0.f, h2 = 0.f, h3 = 0.f;
    float c0 = 0.f, c1 = 0.f, c2 = 0.f, c3 = 0.f;

    // pre[t][b][g*4..g*4+3] as float4; per-t stride = 1024 float4s. The array
    // is padded by 2 timesteps, so prefetching t+2 never needs a clamp.
    const float4* pp = (const float4*)g_pre + (size_t)b * 4 + g;
    float4 cur = pp[0];
    float4 nxt = pp[1024];
    pp += 2048;
    float* op = out + (size_t)b * 4 + g;

    #pragma unroll 2
    for (int t = 0; t < TT; t++) {
        float4 z4 = cur;
        cur = nxt;
        nxt = *pp;              // L2-resident prefetch, 2 steps ahead
        pp += 1024;

        // z = pre + h @ Wh  (packed f32x2)
        unsigned long long z01 = pk2(z4.x, z4.y);
        unsigned long long z23 = pk2(z4.z, z4.w);
        unsigned long long hp;
        hp = pk2(h0, h0); z01 = fma2(hp, wh2[0][0], z01); z23 = fma2(hp, wh2[0][1], z23);
        hp = pk2(h1, h1); z01 = fma2(hp, wh2[1][0], z01); z23 = fma2(hp, wh2[1][1], z23);
        hp = pk2(h2, h2); z01 = fma2(hp, wh2[2][0], z01); z23 = fma2(hp, wh2[2][1], z23);
        hp = pk2(h3, h3); z01 = fma2(hp, wh2[3][0], z01); z23 = fma2(hp, wh2[3][1], z23);
        float z0, z1, z2, z3;
        upk2(z01, z0, z1);
        upk2(z23, z2, z3);

        // qlayer: cumulative product of cosines (tree form)
        float q0 = __cosf(z0);
        float q1 = __cosf(z1);
        float q2 = __cosf(z2);
        float q3 = __cosf(z3);
        float m01 = q0 * q1;
        float p0 = q0;
        float p1 = m01;
        float p2 = m01 * q2;
        float p3 = m01 * (q2 * q3);

        // gate activation via MUFU.TANH
        float a0 = fmaf(asc, tanh_hw(pm * p0), ab);
        float a1 = fmaf(asc, tanh_hw(pm * p1), ab);
        float a2 = fmaf(asc, tanh_hw(pm * p2), ab);
        float a3 = fmaf(asc, tanh_hw(pm * p3), ab);

        // single shuffle round: gather all 4 gates' activation vectors
        float f0 = __shfl_sync(FULL, a0, base);
        float f1 = __shfl_sync(FULL, a1, base);
        float f2 = __shfl_sync(FULL, a2, base);
        float f3 = __shfl_sync(FULL, a3, base);
        float i0 = __shfl_sync(FULL, a0, base + 1);
        float i1 = __shfl_sync(FULL, a1, base + 1);
        float i2 = __shfl_sync(FULL, a2, base + 1);
        float i3 = __shfl_sync(FULL, a3, base + 1);
        float u0 = __shfl_sync(FULL, a0, base + 2);
        float u1 = __shfl_sync(FULL, a1, base + 2);
        float u2 = __shfl_sync(FULL, a2, base + 2);
        float u3 = __shfl_sync(FULL, a3, base + 2);
        float o0 = __shfl_sync(FULL, a0, base + 3);
        float o1 = __shfl_sync(FULL, a1, base + 3);
        float o2 = __shfl_sync(FULL, a2, base + 3);
        float o3 = __shfl_sync(FULL, a3, base + 3);

        // every lane computes the full joint update (identical across quad)
        c0 = fmaf(f0, c0, i0 * u0);
        c1 = fmaf(f1, c1, i1 * u1);
        c2 = fmaf(f2, c2, i2 * u2);
        c3 = fmaf(f3, c3, i3 * u3);

        h0 = o0 * tanh_exp(c0);
        h1 = o1 * tanh_exp(c1);
        h2 = o2 * tanh_exp(c2);
        h3 = o3 * tanh_exp(c3);

        // branch-free store: lane g stores component g (3 SELs + STG.32)
        float hg = (g & 2) ? ((g & 1) ? h3 : h2) : ((g & 1) ? h1 : h0);
        *op = hg;
        op += BB * 4;
    }

    // trailing hx / cx blocks of the tuple output (lane g stores component g)
    float hg = (g & 2) ? ((g & 1) ? h3 : h2) : ((g & 1) ? h1 : h0);
    float cg = (g & 2) ? ((g & 1) ? c3 : c2) : ((g & 1) ? c1 : c0);
    float* hxp = out + (size_t)TT * BB * 4 + (size_t)b * 4 + g;
    float* cxp = out + (size_t)TT * BB * 4 + (size_t)BB * 4 + (size_t)b * 4 + g;
    *hxp = hg;
    *cxp = cg;
}

// ---------------------------------------------------------------------------
extern "C" void kernel_launch(void* const* d_in, const int* in_sizes, int n_in,
                              void* d_out, int out_size) {
    const float* x  = (const float*)d_in[0];
    const float* Wf = (const float*)d_in[1];
    const float* bf = (const float*)d_in[2];
    const float* qf = (const float*)d_in[3];
    const float* Wi = (const float*)d_in[4];
    const float* bi = (const float*)d_in[5];
    const float* qi = (const float*)d_in[6];
    const float* Wu = (const float*)d_in[7];
    const float* bu = (const float*)d_in[8];
    const float* qu = (const float*)d_in[9];
    const float* Wo = (const float*)d_in[10];
    const float* bo = (const float*)d_in[11];
    const float* qo = (const float*)d_in[12];

    qlstm_gemm<<<ROWS / 64, 128>>>(x, Wf, bf, qf, Wi, bi, qi, Wu, bu, qu, Wo, bo, qo);
    qlstm_scan<<<BB / 8, 32>>>(Wf, Wi, Wu, Wo, (float*)d_out);
}